// round 6
// baseline (speedup 1.0000x reference)
#include <cuda_runtime.h>
#include <cuda_bf16.h>
#include <cstdint>

#define VNUM 50000
#define OUTD 128
#define EPS_F 1e-7f
#define WPAD 132   // padded k-row stride for W tiles in shared (conflict-free float4 reads)

// Scratch accumulator for segment_sum result (25.6 MB). Device global: allowed.
__device__ float g_ptr[(size_t)VNUM * OUTD];

// ---------------------------------------------------------------------------
// Kernel 1: zero the accumulator (grid-stride, float4)
// ---------------------------------------------------------------------------
__global__ void zero_kernel() {
    const int n4 = VNUM * OUTD / 4;
    for (int i = blockIdx.x * blockDim.x + threadIdx.x; i < n4;
         i += gridDim.x * blockDim.x) {
        ((float4*)g_ptr)[i] = make_float4(0.f, 0.f, 0.f, 0.f);
    }
}

// ---------------------------------------------------------------------------
// Kernel 2: edge scatter. One warp per edge: 32 lanes x float4 = 128 floats.
// Lanes 0-3 load the edge scalars once; warp distributes via shfl.
// Gather vrepr[sidx] (512B coalesced), scale, red.add.v4 into g_ptr[tidx].
// ---------------------------------------------------------------------------
__global__ void scatter_kernel(const int* __restrict__ sidx,
                               const int* __restrict__ tidx,
                               const float* __restrict__ enorm,
                               const float* __restrict__ esgn,
                               const float* __restrict__ vrepr,
                               int E) {
    int gw = (blockIdx.x * blockDim.x + threadIdx.x) >> 5;
    int lane = threadIdx.x & 31;
    if (gw >= E) return;

    // Deduplicated edge-scalar loads: one LDG per lane 0..3, then broadcast.
    unsigned v32 = 0;
    if (lane == 0)      v32 = (unsigned)__ldg(sidx + gw);
    else if (lane == 1) v32 = (unsigned)__ldg(tidx + gw);
    else if (lane == 2) v32 = __float_as_uint(__ldg(enorm + gw));
    else if (lane == 3) v32 = __float_as_uint(__ldg(esgn + gw));

    int   s = (int)__shfl_sync(0xffffffffu, v32, 0);
    int   t = (int)__shfl_sync(0xffffffffu, v32, 1);
    float w = __uint_as_float(__shfl_sync(0xffffffffu, v32, 2)) *
              __uint_as_float(__shfl_sync(0xffffffffu, v32, 3));

    float4 v = __ldg(((const float4*)vrepr) + (size_t)s * 32 + lane);
    float* dst = g_ptr + (size_t)t * OUTD + lane * 4;
    asm volatile("red.global.add.v4.f32 [%0], {%1, %2, %3, %4};"
                 :: "l"(dst), "f"(v.x * w), "f"(v.y * w), "f"(v.z * w), "f"(v.w * w)
                 : "memory");
}

// ---------------------------------------------------------------------------
// Kernel 3: fused dual GEMM + bias + softplus.
//   loc = ptr @ loc_w.T + loc_b
//   std = softplus(ptr @ std_w.T + std_b) + EPS
// Block: 256 threads, 64 rows per block, full N=128.
// Shared: Wl[k][j] and Ws[k][j] transposed (padded), A tile 64x128.
// Thread (tx, ty): tx in [0,32) owns 4 output cols (float4), ty in [0,8) owns 8 rows.
// ---------------------------------------------------------------------------
__global__ void gemm_kernel(const float* __restrict__ lw,
                            const float* __restrict__ lb,
                            const float* __restrict__ sw,
                            const float* __restrict__ sb,
                            float* __restrict__ out) {
    extern __shared__ float sh[];
    float* shL = sh;                     // 128 * WPAD
    float* shS = sh + 128 * WPAD;        // 128 * WPAD
    float* shA = sh + 2 * 128 * WPAD;    // 64 * 128

    int tid = threadIdx.x;
    int row0 = blockIdx.x * 64;

    // Load W matrices transposed into shared: shX[k*WPAD + j] = X[j*128 + k]
    for (int idx = tid; idx < 128 * 128; idx += 256) {
        int j = idx >> 7;
        int k = idx & 127;
        shL[k * WPAD + j] = lw[idx];
        shS[k * WPAD + j] = sw[idx];
    }
    // Load A tile (64 rows x 128 cols) via float4, coalesced.
    for (int idx = tid; idx < 64 * 32; idx += 256) {
        int r = idx >> 5;
        int c = idx & 31;
        int row = row0 + r;
        float4 v = (row < VNUM) ? ((const float4*)g_ptr)[(size_t)row * 32 + c]
                                : make_float4(0.f, 0.f, 0.f, 0.f);
        ((float4*)shA)[r * 32 + c] = v;
    }
    __syncthreads();

    int tx = tid & 31;   // col group: cols [4*tx, 4*tx+3]
    int ty = tid >> 5;   // row slot: rows [ty*8, ty*8+7] within tile

    float4 accL[8], accS[8];
#pragma unroll
    for (int r = 0; r < 8; r++) {
        accL[r] = make_float4(0.f, 0.f, 0.f, 0.f);
        accS[r] = make_float4(0.f, 0.f, 0.f, 0.f);
    }

    const float* arow = shA + ty * 8 * 128;

#pragma unroll 2
    for (int k = 0; k < 128; k++) {
        float4 wl = *(const float4*)(shL + k * WPAD + tx * 4);
        float4 ws = *(const float4*)(shS + k * WPAD + tx * 4);
#pragma unroll
        for (int r = 0; r < 8; r++) {
            float a = arow[r * 128 + k];   // warp-uniform broadcast
            accL[r].x += a * wl.x; accL[r].y += a * wl.y;
            accL[r].z += a * wl.z; accL[r].w += a * wl.w;
            accS[r].x += a * ws.x; accS[r].y += a * ws.y;
            accS[r].z += a * ws.z; accS[r].w += a * ws.w;
        }
    }

    float4 bl = ((const float4*)lb)[tx];
    float4 bs = ((const float4*)sb)[tx];

    float* out_loc = out;
    float* out_std = out + (size_t)VNUM * OUTD;

#pragma unroll
    for (int r = 0; r < 8; r++) {
        int row = row0 + ty * 8 + r;
        if (row >= VNUM) continue;

        float4 L;
        L.x = accL[r].x + bl.x; L.y = accL[r].y + bl.y;
        L.z = accL[r].z + bl.z; L.w = accL[r].w + bl.w;
        ((float4*)out_loc)[(size_t)row * 32 + tx] = L;

        float4 Sx;
        Sx.x = accS[r].x + bs.x; Sx.y = accS[r].y + bs.y;
        Sx.z = accS[r].z + bs.z; Sx.w = accS[r].w + bs.w;
        // stable softplus: max(x,0) + log1p(exp(-|x|))
        float4 S;
        S.x = fmaxf(Sx.x, 0.f) + log1pf(expf(-fabsf(Sx.x))) + EPS_F;
        S.y = fmaxf(Sx.y, 0.f) + log1pf(expf(-fabsf(Sx.y))) + EPS_F;
        S.z = fmaxf(Sx.z, 0.f) + log1pf(expf(-fabsf(Sx.z))) + EPS_F;
        S.w = fmaxf(Sx.w, 0.f) + log1pf(expf(-fabsf(Sx.w))) + EPS_F;
        ((float4*)out_std)[(size_t)row * 32 + tx] = S;
    }
}

// ---------------------------------------------------------------------------
// Launch
// Inputs (metadata order): sidx, tidx, enorm, esgn, vrepr, loc_w, loc_b, std_w, std_b
// Output: [loc (VNUM*128), std (VNUM*128)] fp32
// ---------------------------------------------------------------------------
extern "C" void kernel_launch(void* const* d_in, const int* in_sizes, int n_in,
                              void* d_out, int out_size) {
    const int*   sidx  = (const int*)d_in[0];
    const int*   tidx  = (const int*)d_in[1];
    const float* enorm = (const float*)d_in[2];
    const float* esgn  = (const float*)d_in[3];
    const float* vrepr = (const float*)d_in[4];
    const float* lw    = (const float*)d_in[5];
    const float* lb    = (const float*)d_in[6];
    const float* sw    = (const float*)d_in[7];
    const float* sb    = (const float*)d_in[8];
    float* out = (float*)d_out;
    int E = in_sizes[0];

    const int smem = (2 * 128 * WPAD + 64 * 128) * (int)sizeof(float); // 167936 B
    (void)cudaFuncSetAttribute(gemm_kernel,
                               cudaFuncAttributeMaxDynamicSharedMemorySize, smem);

    // 1) zero accumulator
    {
        int n4 = VNUM * OUTD / 4;
        int nblk = (n4 + 255) / 256;
        if (nblk > 16384) nblk = 16384;
        zero_kernel<<<nblk, 256>>>();
    }
    // 2) edge scatter: one warp per edge, 8 warps per block
    {
        long long nblk = ((long long)E + 7) / 8;
        scatter_kernel<<<(unsigned)nblk, 256>>>(sidx, tidx, enorm, esgn, vrepr, E);
    }
    // 3) fused dual GEMM + softplus
    {
        int nblk = (VNUM + 63) / 64;
        gemm_kernel<<<nblk, 256, smem>>>(lw, lb, sw, sb, out);
    }
}

// round 9
// speedup vs baseline: 1.1325x; 1.1325x over previous
#include <cuda_runtime.h>
#include <cuda_bf16.h>
#include <cstdint>

#define VNUM 50000
#define OUTD 128
#define EMAX 1600000
#define EPS_F 1e-7f
#define WPAD 132   // padded k-row stride for W tiles in shared (conflict-free float4 reads)

// Device-global scratch (no runtime allocation allowed).
__device__ float g_ptr[(size_t)VNUM * OUTD];   // segment-sum result  (25.6 MB)
__device__ int   g_deg[VNUM];                  // per-target degree
__device__ int   g_off[VNUM + 1];              // CSR offsets (exclusive scan)
__device__ int   g_cursor[VNUM];               // fill cursors
__device__ int2  g_sw[EMAX];                   // packed (sidx, bitcast(weight)) per CSR slot

// ---------------------------------------------------------------------------
// Kernel 1: zero degree counters
// ---------------------------------------------------------------------------
__global__ void zero_deg_kernel() {
    int i = blockIdx.x * blockDim.x + threadIdx.x;
    if (i < VNUM) g_deg[i] = 0;
}

// ---------------------------------------------------------------------------
// Kernel 2: count edges per target (int REDG, spread addresses -> cheap)
// ---------------------------------------------------------------------------
__global__ void count_kernel(const int* __restrict__ tidx, int E) {
    int e = blockIdx.x * blockDim.x + threadIdx.x;
    if (e < E) atomicAdd(&g_deg[__ldg(tidx + e)], 1);
}

// ---------------------------------------------------------------------------
// Kernel 3: exclusive prefix scan of g_deg -> g_off, g_cursor. One block,
// warp-shuffle scan (3 barriers per 1024-chunk, running carry across chunks).
// ---------------------------------------------------------------------------
__global__ void scan_kernel() {
    __shared__ int warp_tot[32];
    __shared__ int carry_sh;
    int tid  = threadIdx.x;
    int lane = tid & 31;
    int wid  = tid >> 5;
    if (tid == 0) carry_sh = 0;
    __syncthreads();

    for (int base = 0; base < VNUM; base += 1024) {
        int i = base + tid;
        int x = (i < VNUM) ? g_deg[i] : 0;

        // intra-warp inclusive scan
        int incl = x;
#pragma unroll
        for (int ofs = 1; ofs < 32; ofs <<= 1) {
            int v = __shfl_up_sync(0xffffffffu, incl, ofs);
            if (lane >= ofs) incl += v;
        }
        if (lane == 31) warp_tot[wid] = incl;
        __syncthreads();

        // warp 0 scans the 32 warp totals (exclusive)
        if (wid == 0) {
            int t = warp_tot[lane];
            int s = t;
#pragma unroll
            for (int ofs = 1; ofs < 32; ofs <<= 1) {
                int v = __shfl_up_sync(0xffffffffu, s, ofs);
                if (lane >= ofs) s += v;
            }
            warp_tot[lane] = s - t;   // exclusive warp offset
        }
        __syncthreads();

        int carry = carry_sh;
        int excl = carry + warp_tot[wid] + incl - x;
        if (i < VNUM) {
            g_off[i] = excl;
            g_cursor[i] = excl;
        }
        __syncthreads();
        if (tid == 1023) carry_sh = carry + warp_tot[31] + incl; // chunk total
        __syncthreads();
    }
    if (tid == 0) g_off[VNUM] = carry_sh;
}

// ---------------------------------------------------------------------------
// Kernel 4: fill CSR slots with packed (source, weight)
// ---------------------------------------------------------------------------
__global__ void fill_kernel(const int* __restrict__ sidx,
                            const int* __restrict__ tidx,
                            const float* __restrict__ enorm,
                            const float* __restrict__ esgn,
                            int E) {
    int e = blockIdx.x * blockDim.x + threadIdx.x;
    if (e >= E) return;
    int t = __ldg(tidx + e);
    int pos = atomicAdd(&g_cursor[t], 1);
    float w = __ldg(enorm + e) * __ldg(esgn + e);
    g_sw[pos] = make_int2(__ldg(sidx + e), __float_as_int(w));
}

// ---------------------------------------------------------------------------
// Kernel 5: gather-aggregate. One warp per target row. Register accumulation,
// single STG.128 per lane. No float atomics anywhere.
// ---------------------------------------------------------------------------
__global__ void gather_kernel(const float* __restrict__ vrepr) {
    int v = (blockIdx.x * blockDim.x + threadIdx.x) >> 5;
    int lane = threadIdx.x & 31;
    if (v >= VNUM) return;

    int beg = __ldg(&g_off[v]);
    int end = __ldg(&g_off[v + 1]);

    float4 acc = make_float4(0.f, 0.f, 0.f, 0.f);
    const float4* vr = (const float4*)vrepr;

    int e = beg;
    // 2-wide unroll for MLP
    for (; e + 1 < end; e += 2) {
        int2 a = __ldg(&g_sw[e]);
        int2 b = __ldg(&g_sw[e + 1]);
        float4 va = __ldg(vr + (size_t)a.x * 32 + lane);
        float4 vb = __ldg(vr + (size_t)b.x * 32 + lane);
        float wa = __int_as_float(a.y);
        float wb = __int_as_float(b.y);
        acc.x += wa * va.x + wb * vb.x;
        acc.y += wa * va.y + wb * vb.y;
        acc.z += wa * va.z + wb * vb.z;
        acc.w += wa * va.w + wb * vb.w;
    }
    if (e < end) {
        int2 a = __ldg(&g_sw[e]);
        float4 va = __ldg(vr + (size_t)a.x * 32 + lane);
        float wa = __int_as_float(a.y);
        acc.x += wa * va.x; acc.y += wa * va.y;
        acc.z += wa * va.z; acc.w += wa * va.w;
    }
    ((float4*)g_ptr)[(size_t)v * 32 + lane] = acc;
}

// ---------------------------------------------------------------------------
// Kernel 6: fused dual GEMM + bias + softplus.
//   loc = ptr @ loc_w.T + loc_b
//   std = softplus(ptr @ std_w.T + std_b) + EPS
// ---------------------------------------------------------------------------
__global__ void gemm_kernel(const float* __restrict__ lw,
                            const float* __restrict__ lb,
                            const float* __restrict__ sw,
                            const float* __restrict__ sb,
                            float* __restrict__ out) {
    extern __shared__ float sh[];
    float* shL = sh;                     // 128 * WPAD
    float* shS = sh + 128 * WPAD;        // 128 * WPAD
    float* shA = sh + 2 * 128 * WPAD;    // 64 * 128

    int tid = threadIdx.x;
    int row0 = blockIdx.x * 64;

    for (int idx = tid; idx < 128 * 128; idx += 256) {
        int j = idx >> 7;
        int k = idx & 127;
        shL[k * WPAD + j] = lw[idx];
        shS[k * WPAD + j] = sw[idx];
    }
    for (int idx = tid; idx < 64 * 32; idx += 256) {
        int r = idx >> 5;
        int c = idx & 31;
        int row = row0 + r;
        float4 v = (row < VNUM) ? ((const float4*)g_ptr)[(size_t)row * 32 + c]
                                : make_float4(0.f, 0.f, 0.f, 0.f);
        ((float4*)shA)[r * 32 + c] = v;
    }
    __syncthreads();

    int tx = tid & 31;
    int ty = tid >> 5;

    float4 accL[8], accS[8];
#pragma unroll
    for (int r = 0; r < 8; r++) {
        accL[r] = make_float4(0.f, 0.f, 0.f, 0.f);
        accS[r] = make_float4(0.f, 0.f, 0.f, 0.f);
    }

    const float* arow = shA + ty * 8 * 128;

#pragma unroll 2
    for (int k = 0; k < 128; k++) {
        float4 wl = *(const float4*)(shL + k * WPAD + tx * 4);
        float4 ws = *(const float4*)(shS + k * WPAD + tx * 4);
#pragma unroll
        for (int r = 0; r < 8; r++) {
            float a = arow[r * 128 + k];
            accL[r].x += a * wl.x; accL[r].y += a * wl.y;
            accL[r].z += a * wl.z; accL[r].w += a * wl.w;
            accS[r].x += a * ws.x; accS[r].y += a * ws.y;
            accS[r].z += a * ws.z; accS[r].w += a * ws.w;
        }
    }

    float4 bl = ((const float4*)lb)[tx];
    float4 bs = ((const float4*)sb)[tx];

    float* out_loc = out;
    float* out_std = out + (size_t)VNUM * OUTD;

#pragma unroll
    for (int r = 0; r < 8; r++) {
        int row = row0 + ty * 8 + r;
        if (row >= VNUM) continue;

        float4 L;
        L.x = accL[r].x + bl.x; L.y = accL[r].y + bl.y;
        L.z = accL[r].z + bl.z; L.w = accL[r].w + bl.w;
        ((float4*)out_loc)[(size_t)row * 32 + tx] = L;

        float4 Sx;
        Sx.x = accS[r].x + bs.x; Sx.y = accS[r].y + bs.y;
        Sx.z = accS[r].z + bs.z; Sx.w = accS[r].w + bs.w;
        float4 S;
        S.x = fmaxf(Sx.x, 0.f) + log1pf(expf(-fabsf(Sx.x))) + EPS_F;
        S.y = fmaxf(Sx.y, 0.f) + log1pf(expf(-fabsf(Sx.y))) + EPS_F;
        S.z = fmaxf(Sx.z, 0.f) + log1pf(expf(-fabsf(Sx.z))) + EPS_F;
        S.w = fmaxf(Sx.w, 0.f) + log1pf(expf(-fabsf(Sx.w))) + EPS_F;
        ((float4*)out_std)[(size_t)row * 32 + tx] = S;
    }
}

// ---------------------------------------------------------------------------
// Launch. Inputs: sidx, tidx, enorm, esgn, vrepr, loc_w, loc_b, std_w, std_b
// Output: [loc (VNUM*128), std (VNUM*128)] fp32
// ---------------------------------------------------------------------------
extern "C" void kernel_launch(void* const* d_in, const int* in_sizes, int n_in,
                              void* d_out, int out_size) {
    const int*   sidx  = (const int*)d_in[0];
    const int*   tidx  = (const int*)d_in[1];
    const float* enorm = (const float*)d_in[2];
    const float* esgn  = (const float*)d_in[3];
    const float* vrepr = (const float*)d_in[4];
    const float* lw    = (const float*)d_in[5];
    const float* lb    = (const float*)d_in[6];
    const float* sw    = (const float*)d_in[7];
    const float* sb    = (const float*)d_in[8];
    float* out = (float*)d_out;
    int E = in_sizes[0];
    if (E > EMAX) E = EMAX;

    const int smem = (2 * 128 * WPAD + 64 * 128) * (int)sizeof(float); // 167936 B
    (void)cudaFuncSetAttribute(gemm_kernel,
                               cudaFuncAttributeMaxDynamicSharedMemorySize, smem);

    // 1) zero degree counters
    zero_deg_kernel<<<(VNUM + 255) / 256, 256>>>();
    // 2) count edges per target
    count_kernel<<<(E + 255) / 256, 256>>>(tidx, E);
    // 3) exclusive scan -> CSR offsets + cursors
    scan_kernel<<<1, 1024>>>();
    // 4) fill CSR with (source, weight)
    fill_kernel<<<(E + 255) / 256, 256>>>(sidx, tidx, enorm, esgn, E);
    // 5) gather-aggregate: one warp per target row
    gather_kernel<<<(VNUM * 32 + 255) / 256, 256>>>(vrepr);
    // 6) fused dual GEMM + softplus
    gemm_kernel<<<(VNUM + 63) / 64, 256, smem>>>(lw, lb, sw, sb, out);
}

// round 10
// speedup vs baseline: 1.7883x; 1.5791x over previous
#include <cuda_runtime.h>
#include <cuda_bf16.h>
#include <cstdint>

#define VNUM 50000
#define OUTD 128
#define EMAX 1600000
#define EPS_F 1e-7f

// Device-global scratch (no runtime allocation allowed).
__device__ float g_ptr[(size_t)VNUM * OUTD];   // segment-sum result  (25.6 MB)
__device__ int   g_deg[VNUM];                  // per-target degree
__device__ int   g_off[VNUM + 1];              // CSR offsets (exclusive scan)
__device__ int   g_cursor[VNUM];               // fill cursors
__device__ int2  g_sw[EMAX];                   // packed (sidx, bitcast(weight)) per CSR slot
__device__ float g_wtL[OUTD * OUTD];           // loc_w transposed: wtL[k*128+j] = lw[j*128+k]
__device__ float g_wtS[OUTD * OUTD];           // std_w transposed

// ---------------------------------------------------------------------------
// Kernel 1: zero degree counters
// ---------------------------------------------------------------------------
__global__ void zero_deg_kernel() {
    int i = blockIdx.x * blockDim.x + threadIdx.x;
    if (i < VNUM) g_deg[i] = 0;
}

// ---------------------------------------------------------------------------
// Kernel 2: count edges per target
// ---------------------------------------------------------------------------
__global__ void count_kernel(const int* __restrict__ tidx, int E) {
    int e = blockIdx.x * blockDim.x + threadIdx.x;
    if (e < E) atomicAdd(&g_deg[__ldg(tidx + e)], 1);
}

// ---------------------------------------------------------------------------
// Kernel 3: exclusive prefix scan of g_deg -> g_off, g_cursor. One block,
// warp-shuffle scan, running carry across 1024-chunks.
// ---------------------------------------------------------------------------
__global__ void scan_kernel() {
    __shared__ int warp_tot[32];
    __shared__ int carry_sh;
    int tid  = threadIdx.x;
    int lane = tid & 31;
    int wid  = tid >> 5;
    if (tid == 0) carry_sh = 0;
    __syncthreads();

    for (int base = 0; base < VNUM; base += 1024) {
        int i = base + tid;
        int x = (i < VNUM) ? g_deg[i] : 0;

        int incl = x;
#pragma unroll
        for (int ofs = 1; ofs < 32; ofs <<= 1) {
            int v = __shfl_up_sync(0xffffffffu, incl, ofs);
            if (lane >= ofs) incl += v;
        }
        if (lane == 31) warp_tot[wid] = incl;
        __syncthreads();

        if (wid == 0) {
            int t = warp_tot[lane];
            int s = t;
#pragma unroll
            for (int ofs = 1; ofs < 32; ofs <<= 1) {
                int v = __shfl_up_sync(0xffffffffu, s, ofs);
                if (lane >= ofs) s += v;
            }
            warp_tot[lane] = s - t;   // exclusive warp offset
        }
        __syncthreads();

        int carry = carry_sh;
        int excl = carry + warp_tot[wid] + incl - x;
        if (i < VNUM) {
            g_off[i] = excl;
            g_cursor[i] = excl;
        }
        __syncthreads();
        if (tid == 1023) carry_sh = carry + warp_tot[31] + incl;
        __syncthreads();
    }
    if (tid == 0) g_off[VNUM] = carry_sh;
}

// ---------------------------------------------------------------------------
// Kernel 4: fill CSR slots with packed (source, weight)
// ---------------------------------------------------------------------------
__global__ void fill_kernel(const int* __restrict__ sidx,
                            const int* __restrict__ tidx,
                            const float* __restrict__ enorm,
                            const float* __restrict__ esgn,
                            int E) {
    int e = blockIdx.x * blockDim.x + threadIdx.x;
    if (e >= E) return;
    int t = __ldg(tidx + e);
    int pos = atomicAdd(&g_cursor[t], 1);
    float w = __ldg(enorm + e) * __ldg(esgn + e);
    g_sw[pos] = make_int2(__ldg(sidx + e), __float_as_int(w));
}

// ---------------------------------------------------------------------------
// Kernel 5: transpose the two weight matrices into device scratch.
// Coalesced reads; scattered writes (tiny: 128 KB total, one-shot).
// ---------------------------------------------------------------------------
__global__ void wtrans_kernel(const float* __restrict__ lw,
                              const float* __restrict__ sw) {
    int idx = blockIdx.x * blockDim.x + threadIdx.x;
    if (idx < OUTD * OUTD) {
        int j = idx >> 7;
        int k = idx & 127;
        g_wtL[k * OUTD + j] = lw[idx];
        g_wtS[k * OUTD + j] = sw[idx];
    }
}

// ---------------------------------------------------------------------------
// Kernel 6: gather-aggregate v2. One warp per target row.
// Warp cooperatively loads 32 edge records with ONE coalesced 256B load,
// then broadcasts via shfl and issues 4 independent row-gathers per step
// (MLP ~4-8). Register accumulation, one STG.128 per lane, no float atomics.
// ---------------------------------------------------------------------------
__global__ void gather_kernel(const float* __restrict__ vrepr) {
    int v = (blockIdx.x * blockDim.x + threadIdx.x) >> 5;
    int lane = threadIdx.x & 31;
    if (v >= VNUM) return;

    int beg = __ldg(&g_off[v]);
    int end = __ldg(&g_off[v + 1]);

    float4 acc = make_float4(0.f, 0.f, 0.f, 0.f);
    const float4* vr = (const float4*)vrepr;
    const unsigned FULL = 0xffffffffu;

    for (int base = beg; base < end; base += 32) {
        int rem = end - base;
        int n = rem < 32 ? rem : 32;
        int2 rec = make_int2(0, 0);
        if (lane < n) rec = __ldg(&g_sw[base + lane]);

        if (n == 32) {
#pragma unroll
            for (int j = 0; j < 32; j += 4) {
                int s0 = __shfl_sync(FULL, rec.x, j);
                int s1 = __shfl_sync(FULL, rec.x, j + 1);
                int s2 = __shfl_sync(FULL, rec.x, j + 2);
                int s3 = __shfl_sync(FULL, rec.x, j + 3);
                float w0 = __int_as_float(__shfl_sync(FULL, rec.y, j));
                float w1 = __int_as_float(__shfl_sync(FULL, rec.y, j + 1));
                float w2 = __int_as_float(__shfl_sync(FULL, rec.y, j + 2));
                float w3 = __int_as_float(__shfl_sync(FULL, rec.y, j + 3));
                float4 v0 = __ldg(vr + (size_t)s0 * 32 + lane);
                float4 v1 = __ldg(vr + (size_t)s1 * 32 + lane);
                float4 v2 = __ldg(vr + (size_t)s2 * 32 + lane);
                float4 v3 = __ldg(vr + (size_t)s3 * 32 + lane);
                acc.x += w0 * v0.x + w1 * v1.x + w2 * v2.x + w3 * v3.x;
                acc.y += w0 * v0.y + w1 * v1.y + w2 * v2.y + w3 * v3.y;
                acc.z += w0 * v0.z + w1 * v1.z + w2 * v2.z + w3 * v3.z;
                acc.w += w0 * v0.w + w1 * v1.w + w2 * v2.w + w3 * v3.w;
            }
        } else {
            for (int j = 0; j < n; j++) {
                int s = __shfl_sync(FULL, rec.x, j);
                float w = __int_as_float(__shfl_sync(FULL, rec.y, j));
                float4 va = __ldg(vr + (size_t)s * 32 + lane);
                acc.x += w * va.x; acc.y += w * va.y;
                acc.z += w * va.z; acc.w += w * va.w;
            }
        }
    }
    ((float4*)g_ptr)[(size_t)v * 32 + lane] = acc;
}

// ---------------------------------------------------------------------------
// Kernel 7: fused dual GEMM + bias + softplus.
//   loc = ptr @ loc_w.T + loc_b ; std = softplus(ptr @ std_w.T + std_b) + EPS
// W read as transposed rows via __ldg (L1-resident, broadcast across blocks).
// Only the 64x128 A tile lives in shared (32 KB static) -> 3-4 blocks/SM.
// ---------------------------------------------------------------------------
__global__ void gemm_kernel(const float* __restrict__ lb,
                            const float* __restrict__ sb,
                            float* __restrict__ out) {
    __shared__ float shA[64 * 128];

    int tid = threadIdx.x;
    int row0 = blockIdx.x * 64;

    for (int idx = tid; idx < 64 * 32; idx += 256) {
        int r = idx >> 5;
        int c = idx & 31;
        int row = row0 + r;
        float4 v = (row < VNUM) ? ((const float4*)g_ptr)[(size_t)row * 32 + c]
                                : make_float4(0.f, 0.f, 0.f, 0.f);
        ((float4*)shA)[r * 32 + c] = v;
    }
    __syncthreads();

    int tx = tid & 31;   // col group: cols [4*tx, 4*tx+3]
    int ty = tid >> 5;   // row slot: rows [ty*8, ty*8+7] within tile

    float4 accL[8], accS[8];
#pragma unroll
    for (int r = 0; r < 8; r++) {
        accL[r] = make_float4(0.f, 0.f, 0.f, 0.f);
        accS[r] = make_float4(0.f, 0.f, 0.f, 0.f);
    }

    const float* arow = shA + ty * 8 * 128;
    const float4* wL4 = (const float4*)g_wtL;
    const float4* wS4 = (const float4*)g_wtS;

#pragma unroll 2
    for (int k = 0; k < 128; k++) {
        float4 wl = __ldg(wL4 + k * 32 + tx);
        float4 ws = __ldg(wS4 + k * 32 + tx);
#pragma unroll
        for (int r = 0; r < 8; r++) {
            float a = arow[r * 128 + k];   // warp-uniform broadcast
            accL[r].x += a * wl.x; accL[r].y += a * wl.y;
            accL[r].z += a * wl.z; accL[r].w += a * wl.w;
            accS[r].x += a * ws.x; accS[r].y += a * ws.y;
            accS[r].z += a * ws.z; accS[r].w += a * ws.w;
        }
    }

    float4 bl = ((const float4*)lb)[tx];
    float4 bs = ((const float4*)sb)[tx];

    float* out_loc = out;
    float* out_std = out + (size_t)VNUM * OUTD;

#pragma unroll
    for (int r = 0; r < 8; r++) {
        int row = row0 + ty * 8 + r;
        if (row >= VNUM) continue;

        float4 L;
        L.x = accL[r].x + bl.x; L.y = accL[r].y + bl.y;
        L.z = accL[r].z + bl.z; L.w = accL[r].w + bl.w;
        ((float4*)out_loc)[(size_t)row * 32 + tx] = L;

        float4 Sx;
        Sx.x = accS[r].x + bs.x; Sx.y = accS[r].y + bs.y;
        Sx.z = accS[r].z + bs.z; Sx.w = accS[r].w + bs.w;
        float4 S;
        S.x = fmaxf(Sx.x, 0.f) + log1pf(expf(-fabsf(Sx.x))) + EPS_F;
        S.y = fmaxf(Sx.y, 0.f) + log1pf(expf(-fabsf(Sx.y))) + EPS_F;
        S.z = fmaxf(Sx.z, 0.f) + log1pf(expf(-fabsf(Sx.z))) + EPS_F;
        S.w = fmaxf(Sx.w, 0.f) + log1pf(expf(-fabsf(Sx.w))) + EPS_F;
        ((float4*)out_std)[(size_t)row * 32 + tx] = S;
    }
}

// ---------------------------------------------------------------------------
// Launch. Inputs: sidx, tidx, enorm, esgn, vrepr, loc_w, loc_b, std_w, std_b
// Output: [loc (VNUM*128), std (VNUM*128)] fp32
// ---------------------------------------------------------------------------
extern "C" void kernel_launch(void* const* d_in, const int* in_sizes, int n_in,
                              void* d_out, int out_size) {
    const int*   sidx  = (const int*)d_in[0];
    const int*   tidx  = (const int*)d_in[1];
    const float* enorm = (const float*)d_in[2];
    const float* esgn  = (const float*)d_in[3];
    const float* vrepr = (const float*)d_in[4];
    const float* lw    = (const float*)d_in[5];
    const float* lb    = (const float*)d_in[6];
    const float* sw    = (const float*)d_in[7];
    const float* sb    = (const float*)d_in[8];
    float* out = (float*)d_out;
    int E = in_sizes[0];
    if (E > EMAX) E = EMAX;

    // 1) zero degree counters
    zero_deg_kernel<<<(VNUM + 255) / 256, 256>>>();
    // 2) count edges per target
    count_kernel<<<(E + 255) / 256, 256>>>(tidx, E);
    // 3) exclusive scan -> CSR offsets + cursors
    scan_kernel<<<1, 1024>>>();
    // 4) fill CSR with (source, weight)
    fill_kernel<<<(E + 255) / 256, 256>>>(sidx, tidx, enorm, esgn, E);
    // 5) transpose weights into scratch
    wtrans_kernel<<<(OUTD * OUTD + 255) / 256, 256>>>(lw, sw);
    // 6) gather-aggregate: one warp per target row, batched edge loads
    gather_kernel<<<(VNUM * 32 + 255) / 256, 256>>>(vrepr);
    // 7) fused dual GEMM + softplus
    gemm_kernel<<<(VNUM + 63) / 64, 256>>>(lb, sb, out);
}

// round 14
// speedup vs baseline: 1.8358x; 1.0266x over previous
#include <cuda_runtime.h>
#include <cuda_bf16.h>
#include <cstdint>

#define VNUM 50000
#define OUTD 128
#define EMAX 1600000
#define EPS_F 1e-7f
#define PADK 136                       // padded k-stride (bf16 elems) -> conflict-free frags

// ---------------------------------------------------------------------------
// Device-global scratch (no runtime allocation allowed).
// ---------------------------------------------------------------------------
__device__ float g_ptr[(size_t)VNUM * OUTD];   // segment-sum result (25.6 MB)
__device__ int   g_deg[VNUM];
__device__ int   g_off[VNUM + 1];
__device__ int   g_cursor[VNUM];
__device__ int2  g_sw[EMAX];                   // packed (sidx, bitcast(weight))
// B = [loc_w ; std_w] as 256 rows x 128 k, bf16 hi/lo, row-major.
__device__ __align__(16) __nv_bfloat16 g_Bhi[256 * 128];
__device__ __align__(16) __nv_bfloat16 g_Blo[256 * 128];

// ---------------------------------------------------------------------------
// mma.sync m16n8k16 bf16 (baseline sm_80+ PTX -- no sm_103a features needed)
// ---------------------------------------------------------------------------
__device__ __forceinline__ void mma16816(float* c, const uint32_t* a, const uint32_t* b) {
    asm volatile(
        "mma.sync.aligned.m16n8k16.row.col.f32.bf16.bf16.f32 "
        "{%0,%1,%2,%3}, {%4,%5,%6,%7}, {%8,%9}, {%0,%1,%2,%3};"
        : "+f"(c[0]), "+f"(c[1]), "+f"(c[2]), "+f"(c[3])
        : "r"(a[0]), "r"(a[1]), "r"(a[2]), "r"(a[3]), "r"(b[0]), "r"(b[1]));
}

// ---------------------------------------------------------------------------
// Kernel 1: zero degree counters
// ---------------------------------------------------------------------------
__global__ void zero_deg_kernel() {
    int i = blockIdx.x * blockDim.x + threadIdx.x;
    if (i < VNUM) g_deg[i] = 0;
}

// ---------------------------------------------------------------------------
// Kernel 2: count edges per target, 4 edges per thread (int4 loads, MLP=4)
// ---------------------------------------------------------------------------
__global__ void count_kernel(const int* __restrict__ tidx, int E) {
    int i = (blockIdx.x * blockDim.x + threadIdx.x) * 4;
    if (i + 3 < E) {
        int4 t = __ldg((const int4*)(tidx + i));
        atomicAdd(&g_deg[t.x], 1);
        atomicAdd(&g_deg[t.y], 1);
        atomicAdd(&g_deg[t.z], 1);
        atomicAdd(&g_deg[t.w], 1);
    } else {
        for (int e = i; e < E; e++) atomicAdd(&g_deg[__ldg(tidx + e)], 1);
    }
}

// ---------------------------------------------------------------------------
// Kernel 3: exclusive scan -> g_off, g_cursor. One block, warp-shuffle scan.
// ---------------------------------------------------------------------------
__global__ void scan_kernel() {
    __shared__ int warp_tot[32];
    __shared__ int carry_sh;
    int tid  = threadIdx.x;
    int lane = tid & 31;
    int wid  = tid >> 5;
    if (tid == 0) carry_sh = 0;
    __syncthreads();

    for (int base = 0; base < VNUM; base += 1024) {
        int i = base + tid;
        int x = (i < VNUM) ? g_deg[i] : 0;

        int incl = x;
#pragma unroll
        for (int ofs = 1; ofs < 32; ofs <<= 1) {
            int v = __shfl_up_sync(0xffffffffu, incl, ofs);
            if (lane >= ofs) incl += v;
        }
        if (lane == 31) warp_tot[wid] = incl;
        __syncthreads();

        if (wid == 0) {
            int t = warp_tot[lane];
            int s = t;
#pragma unroll
            for (int ofs = 1; ofs < 32; ofs <<= 1) {
                int v = __shfl_up_sync(0xffffffffu, s, ofs);
                if (lane >= ofs) s += v;
            }
            warp_tot[lane] = s - t;
        }
        __syncthreads();

        int carry = carry_sh;
        int excl = carry + warp_tot[wid] + incl - x;
        if (i < VNUM) {
            g_off[i] = excl;
            g_cursor[i] = excl;
        }
        __syncthreads();
        if (tid == 1023) carry_sh = carry + warp_tot[31] + incl;
        __syncthreads();
    }
    if (tid == 0) g_off[VNUM] = carry_sh;
}

// ---------------------------------------------------------------------------
// Kernel 4: fill CSR slots, 4 edges per thread (vector loads, MLP=4)
// ---------------------------------------------------------------------------
__global__ void fill_kernel(const int* __restrict__ sidx,
                            const int* __restrict__ tidx,
                            const float* __restrict__ enorm,
                            const float* __restrict__ esgn,
                            int E) {
    int i = (blockIdx.x * blockDim.x + threadIdx.x) * 4;
    if (i + 3 < E) {
        int4   s = __ldg((const int4*)(sidx + i));
        int4   t = __ldg((const int4*)(tidx + i));
        float4 n = __ldg((const float4*)(enorm + i));
        float4 g = __ldg((const float4*)(esgn + i));
        int p0 = atomicAdd(&g_cursor[t.x], 1);
        int p1 = atomicAdd(&g_cursor[t.y], 1);
        int p2 = atomicAdd(&g_cursor[t.z], 1);
        int p3 = atomicAdd(&g_cursor[t.w], 1);
        g_sw[p0] = make_int2(s.x, __float_as_int(n.x * g.x));
        g_sw[p1] = make_int2(s.y, __float_as_int(n.y * g.y));
        g_sw[p2] = make_int2(s.z, __float_as_int(n.z * g.z));
        g_sw[p3] = make_int2(s.w, __float_as_int(n.w * g.w));
    } else {
        for (int e = i; e < E; e++) {
            int t = __ldg(tidx + e);
            int pos = atomicAdd(&g_cursor[t], 1);
            float w = __ldg(enorm + e) * __ldg(esgn + e);
            g_sw[pos] = make_int2(__ldg(sidx + e), __float_as_int(w));
        }
    }
}

// ---------------------------------------------------------------------------
// Kernel 5: split weights to bf16 hi/lo, row-major [256][128].
// Row n: n<128 -> loc_w row n; n>=128 -> std_w row n-128.
// ---------------------------------------------------------------------------
__global__ void wconv_kernel(const float* __restrict__ lw,
                             const float* __restrict__ sw) {
    int idx = blockIdx.x * blockDim.x + threadIdx.x;
    if (idx >= 256 * 128) return;
    int n = idx >> 7;
    int k = idx & 127;
    float w = (n < 128) ? lw[n * 128 + k] : sw[(n - 128) * 128 + k];
    __nv_bfloat16 hi = __float2bfloat16(w);
    __nv_bfloat16 lo = __float2bfloat16(w - __bfloat162float(hi));
    g_Bhi[idx] = hi;
    g_Blo[idx] = lo;
}

// ---------------------------------------------------------------------------
// Kernel 6: gather-aggregate (proven R10 version). One warp per target row,
// batched coalesced edge loads + shfl broadcast, 4-deep gather MLP,
// register accumulation, one STG.128 per lane. No float atomics.
// ---------------------------------------------------------------------------
__global__ void gather_kernel(const float* __restrict__ vrepr) {
    int v = (blockIdx.x * blockDim.x + threadIdx.x) >> 5;
    int lane = threadIdx.x & 31;
    if (v >= VNUM) return;

    int beg = __ldg(&g_off[v]);
    int end = __ldg(&g_off[v + 1]);

    float4 acc = make_float4(0.f, 0.f, 0.f, 0.f);
    const float4* vr = (const float4*)vrepr;
    const unsigned FULL = 0xffffffffu;

    for (int base = beg; base < end; base += 32) {
        int rem = end - base;
        int n = rem < 32 ? rem : 32;
        int2 rec = make_int2(0, 0);
        if (lane < n) rec = __ldg(&g_sw[base + lane]);

        if (n == 32) {
#pragma unroll
            for (int j = 0; j < 32; j += 4) {
                int s0 = __shfl_sync(FULL, rec.x, j);
                int s1 = __shfl_sync(FULL, rec.x, j + 1);
                int s2 = __shfl_sync(FULL, rec.x, j + 2);
                int s3 = __shfl_sync(FULL, rec.x, j + 3);
                float w0 = __int_as_float(__shfl_sync(FULL, rec.y, j));
                float w1 = __int_as_float(__shfl_sync(FULL, rec.y, j + 1));
                float w2 = __int_as_float(__shfl_sync(FULL, rec.y, j + 2));
                float w3 = __int_as_float(__shfl_sync(FULL, rec.y, j + 3));
                float4 v0 = __ldg(vr + (size_t)s0 * 32 + lane);
                float4 v1 = __ldg(vr + (size_t)s1 * 32 + lane);
                float4 v2 = __ldg(vr + (size_t)s2 * 32 + lane);
                float4 v3 = __ldg(vr + (size_t)s3 * 32 + lane);
                acc.x += w0 * v0.x + w1 * v1.x + w2 * v2.x + w3 * v3.x;
                acc.y += w0 * v0.y + w1 * v1.y + w2 * v2.y + w3 * v3.y;
                acc.z += w0 * v0.z + w1 * v1.z + w2 * v2.z + w3 * v3.z;
                acc.w += w0 * v0.w + w1 * v1.w + w2 * v2.w + w3 * v3.w;
            }
        } else {
            for (int j = 0; j < n; j++) {
                int s = __shfl_sync(FULL, rec.x, j);
                float w = __int_as_float(__shfl_sync(FULL, rec.y, j));
                float4 va = __ldg(vr + (size_t)s * 32 + lane);
                acc.x += w * va.x; acc.y += w * va.y;
                acc.z += w * va.z; acc.w += w * va.w;
            }
        }
    }
    ((float4*)g_ptr)[(size_t)v * 32 + lane] = acc;
}

// ---------------------------------------------------------------------------
// Kernel 7: dual GEMM + bias + softplus via mma.sync bf16 3-split.
//   D = Ahi*Bhi + Alo*Bhi + Ahi*Blo   (error ~2^-16)
// Block: 256 threads / 8 warps, 64 rows x 256 cols (N=256 = loc|std).
// Warp (m_tile 0..3, col_half 0..1): 16 rows x 128 cols = 16 n-tiles of m16n8k16.
// SMEM: A hi/lo 64x136, B hi/lo 256x136 (padded, conflict-free frags) = 174 KB.
// ---------------------------------------------------------------------------
#define SM_AHI 0
#define SM_ALO (64 * PADK * 2)                     // 17408
#define SM_BHI (2 * 64 * PADK * 2)                 // 34816
#define SM_BLO (2 * 64 * PADK * 2 + 256 * PADK * 2)// 104448
#define GEMM_SMEM (2 * 64 * PADK * 2 + 2 * 256 * PADK * 2)  // 174080

__global__ void __launch_bounds__(256, 1)
gemm_kernel(const float* __restrict__ lb,
            const float* __restrict__ sb,
            float* __restrict__ out) {
    extern __shared__ __align__(16) uint8_t smem[];
    __nv_bfloat16* shAhi = (__nv_bfloat16*)(smem + SM_AHI);
    __nv_bfloat16* shAlo = (__nv_bfloat16*)(smem + SM_ALO);
    __nv_bfloat16* shBhi = (__nv_bfloat16*)(smem + SM_BHI);
    __nv_bfloat16* shBlo = (__nv_bfloat16*)(smem + SM_BLO);

    int tid = threadIdx.x;
    int row0 = blockIdx.x * 64;

    // Stage A: read fp32 g_ptr, split into bf16 hi/lo. 2048 float4 / 256 thr.
    for (int i = tid; i < 2048; i += 256) {
        int r = i >> 5;            // 0..63
        int c4 = i & 31;           // float4 index -> cols c4*4..c4*4+3
        int row = row0 + r;
        float4 v = (row < VNUM) ? __ldg((const float4*)g_ptr + (size_t)row * 32 + c4)
                                : make_float4(0.f, 0.f, 0.f, 0.f);
        __nv_bfloat16 h0 = __float2bfloat16(v.x), h1 = __float2bfloat16(v.y);
        __nv_bfloat16 h2 = __float2bfloat16(v.z), h3 = __float2bfloat16(v.w);
        __nv_bfloat16 l0 = __float2bfloat16(v.x - __bfloat162float(h0));
        __nv_bfloat16 l1 = __float2bfloat16(v.y - __bfloat162float(h1));
        __nv_bfloat16 l2 = __float2bfloat16(v.z - __bfloat162float(h2));
        __nv_bfloat16 l3 = __float2bfloat16(v.w - __bfloat162float(h3));
        uint2 hp, lp;
        hp.x = (uint32_t)__bfloat16_as_ushort(h0) | ((uint32_t)__bfloat16_as_ushort(h1) << 16);
        hp.y = (uint32_t)__bfloat16_as_ushort(h2) | ((uint32_t)__bfloat16_as_ushort(h3) << 16);
        lp.x = (uint32_t)__bfloat16_as_ushort(l0) | ((uint32_t)__bfloat16_as_ushort(l1) << 16);
        lp.y = (uint32_t)__bfloat16_as_ushort(l2) | ((uint32_t)__bfloat16_as_ushort(l3) << 16);
        *(uint2*)(shAhi + r * PADK + c4 * 4) = hp;
        *(uint2*)(shAlo + r * PADK + c4 * 4) = lp;
    }
    // Stage B: 256 rows x 16 uint4 (8 bf16 each) per matrix.
    for (int i = tid; i < 4096; i += 256) {
        int n = i >> 4;
        int c8 = i & 15;           // cols c8*8..c8*8+7
        *(uint4*)(shBhi + n * PADK + c8 * 8) = *((const uint4*)g_Bhi + (size_t)n * 16 + c8);
        *(uint4*)(shBlo + n * PADK + c8 * 8) = *((const uint4*)g_Blo + (size_t)n * 16 + c8);
    }
    __syncthreads();

    int warp = tid >> 5;
    int lane = tid & 31;
    int warp_m = warp & 3;         // 4 m-tiles of 16 rows
    int col_half = warp >> 1 >> 1; // warp>>2: 0..1
    int g = lane >> 2;             // group row 0..7
    int tg = lane & 3;             // thread-in-group

    const __nv_bfloat16* Ah = shAhi + (warp_m * 16 + g) * PADK;
    const __nv_bfloat16* Al = shAlo + (warp_m * 16 + g) * PADK;

    float acc[16][4];
#pragma unroll
    for (int t = 0; t < 16; t++)
        acc[t][0] = acc[t][1] = acc[t][2] = acc[t][3] = 0.f;

#pragma unroll
    for (int ks = 0; ks < 8; ks++) {
        int k0 = ks * 16 + tg * 2;
        uint32_t ah[4], al[4];
        ah[0] = *(const uint32_t*)(Ah + k0);
        ah[1] = *(const uint32_t*)(Ah + 8 * PADK + k0);
        ah[2] = *(const uint32_t*)(Ah + k0 + 8);
        ah[3] = *(const uint32_t*)(Ah + 8 * PADK + k0 + 8);
        al[0] = *(const uint32_t*)(Al + k0);
        al[1] = *(const uint32_t*)(Al + 8 * PADK + k0);
        al[2] = *(const uint32_t*)(Al + k0 + 8);
        al[3] = *(const uint32_t*)(Al + 8 * PADK + k0 + 8);

#pragma unroll
        for (int nt = 0; nt < 16; nt++) {
            int n = col_half * 128 + nt * 8 + g;
            const __nv_bfloat16* Bh = shBhi + n * PADK;
            const __nv_bfloat16* Bl = shBlo + n * PADK;
            uint32_t bh[2], bl[2];
            bh[0] = *(const uint32_t*)(Bh + k0);
            bh[1] = *(const uint32_t*)(Bh + k0 + 8);
            bl[0] = *(const uint32_t*)(Bl + k0);
            bl[1] = *(const uint32_t*)(Bl + k0 + 8);
            mma16816(acc[nt], ah, bh);
            mma16816(acc[nt], al, bh);
            mma16816(acc[nt], ah, bl);
        }
    }

    // Epilogue: c0,c1 -> row g cols tg*2,+1 ; c2,c3 -> row g+8 same cols.
    int row_a = row0 + warp_m * 16 + g;
    int row_b = row_a + 8;
    float* out_loc = out;
    float* out_std = out + (size_t)VNUM * OUTD;

#pragma unroll
    for (int nt = 0; nt < 16; nt++) {
        int ncol = col_half * 128 + nt * 8 + tg * 2;
        if (ncol < 128) {
            float b0 = __ldg(lb + ncol), b1 = __ldg(lb + ncol + 1);
            if (row_a < VNUM) {
                float2 o = make_float2(acc[nt][0] + b0, acc[nt][1] + b1);
                *(float2*)(out_loc + (size_t)row_a * OUTD + ncol) = o;
            }
            if (row_b < VNUM) {
                float2 o = make_float2(acc[nt][2] + b0, acc[nt][3] + b1);
                *(float2*)(out_loc + (size_t)row_b * OUTD + ncol) = o;
            }
        } else {
            int sc = ncol - 128;
            float b0 = __ldg(sb + sc), b1 = __ldg(sb + sc + 1);
            if (row_a < VNUM) {
                float x0 = acc[nt][0] + b0, x1 = acc[nt][1] + b1;
                float2 o;
                o.x = fmaxf(x0, 0.f) + log1pf(expf(-fabsf(x0))) + EPS_F;
                o.y = fmaxf(x1, 0.f) + log1pf(expf(-fabsf(x1))) + EPS_F;
                *(float2*)(out_std + (size_t)row_a * OUTD + sc) = o;
            }
            if (row_b < VNUM) {
                float x0 = acc[nt][2] + b0, x1 = acc[nt][3] + b1;
                float2 o;
                o.x = fmaxf(x0, 0.f) + log1pf(expf(-fabsf(x0))) + EPS_F;
                o.y = fmaxf(x1, 0.f) + log1pf(expf(-fabsf(x1))) + EPS_F;
                *(float2*)(out_std + (size_t)row_b * OUTD + sc) = o;
            }
        }
    }
}

// ---------------------------------------------------------------------------
// Launch. Inputs: sidx, tidx, enorm, esgn, vrepr, loc_w, loc_b, std_w, std_b
// Output: [loc (VNUM*128), std (VNUM*128)] fp32
// ---------------------------------------------------------------------------
extern "C" void kernel_launch(void* const* d_in, const int* in_sizes, int n_in,
                              void* d_out, int out_size) {
    const int*   sidx  = (const int*)d_in[0];
    const int*   tidx  = (const int*)d_in[1];
    const float* enorm = (const float*)d_in[2];
    const float* esgn  = (const float*)d_in[3];
    const float* vrepr = (const float*)d_in[4];
    const float* lw    = (const float*)d_in[5];
    const float* lb    = (const float*)d_in[6];
    const float* sw    = (const float*)d_in[7];
    const float* sb    = (const float*)d_in[8];
    float* out = (float*)d_out;
    int E = in_sizes[0];
    if (E > EMAX) E = EMAX;

    (void)cudaFuncSetAttribute(gemm_kernel,
                               cudaFuncAttributeMaxDynamicSharedMemorySize, GEMM_SMEM);

    // 1) zero degree counters
    zero_deg_kernel<<<(VNUM + 255) / 256, 256>>>();
    // 2) count edges per target (4/thread)
    count_kernel<<<((E + 3) / 4 + 255) / 256, 256>>>(tidx, E);
    // 3) exclusive scan -> CSR offsets + cursors
    scan_kernel<<<1, 1024>>>();
    // 4) fill CSR (4/thread)
    fill_kernel<<<((E + 3) / 4 + 255) / 256, 256>>>(sidx, tidx, enorm, esgn, E);
    // 5) weights -> bf16 hi/lo
    wconv_kernel<<<(256 * 128 + 255) / 256, 256>>>(lw, sw);
    // 6) gather-aggregate -> fp32 ptr
    gather_kernel<<<(VNUM * 32 + 255) / 256, 256>>>(vrepr);
    // 7) dual GEMM + bias + softplus (mma.sync bf16 3-split)
    gemm_kernel<<<(VNUM + 63) / 64, 256, GEMM_SMEM>>>(lb, sb, out);
}

// round 15
// speedup vs baseline: 1.9620x; 1.0687x over previous
#include <cuda_runtime.h>
#include <cuda_bf16.h>
#include <cuda_fp16.h>
#include <cstdint>

#define VNUM 50000
#define OUTD 128
#define EMAX 1600000
#define EPS_F 1e-7f
#define PADK 136                       // padded k-stride (bf16 elems) -> conflict-free frags

// ---------------------------------------------------------------------------
// Device-global scratch (no runtime allocation allowed).
// ---------------------------------------------------------------------------
__device__ float g_ptr[(size_t)VNUM * OUTD];   // segment-sum result (25.6 MB)
__device__ int   g_deg[VNUM];
__device__ int   g_off[VNUM + 1];
__device__ int   g_cursor[VNUM];
__device__ int2  g_sw[EMAX];                   // packed (sidx, bitcast(weight))
__device__ __align__(16) __half g_vrh[(size_t)VNUM * OUTD];  // fp16 vrepr (12.8 MB)
// B = [loc_w ; std_w] as 256 rows x 128 k, bf16 hi/lo, row-major.
__device__ __align__(16) __nv_bfloat16 g_Bhi[256 * 128];
__device__ __align__(16) __nv_bfloat16 g_Blo[256 * 128];

// ---------------------------------------------------------------------------
// mma.sync m16n8k16 bf16 (baseline sm_80+ PTX -- no sm_103a features needed)
// ---------------------------------------------------------------------------
__device__ __forceinline__ void mma16816(float* c, const uint32_t* a, const uint32_t* b) {
    asm volatile(
        "mma.sync.aligned.m16n8k16.row.col.f32.bf16.bf16.f32 "
        "{%0,%1,%2,%3}, {%4,%5,%6,%7}, {%8,%9}, {%0,%1,%2,%3};"
        : "+f"(c[0]), "+f"(c[1]), "+f"(c[2]), "+f"(c[3])
        : "r"(a[0]), "r"(a[1]), "r"(a[2]), "r"(a[3]), "r"(b[0]), "r"(b[1]));
}

// ---------------------------------------------------------------------------
// Kernel 1: zero degree counters
// ---------------------------------------------------------------------------
__global__ void zero_deg_kernel() {
    int i = blockIdx.x * blockDim.x + threadIdx.x;
    if (i < VNUM) g_deg[i] = 0;
}

// ---------------------------------------------------------------------------
// Kernel 2: count edges per target, 4 edges per thread (int4 loads, MLP=4)
// ---------------------------------------------------------------------------
__global__ void count_kernel(const int* __restrict__ tidx, int E) {
    int i = (blockIdx.x * blockDim.x + threadIdx.x) * 4;
    if (i + 3 < E) {
        int4 t = __ldg((const int4*)(tidx + i));
        atomicAdd(&g_deg[t.x], 1);
        atomicAdd(&g_deg[t.y], 1);
        atomicAdd(&g_deg[t.z], 1);
        atomicAdd(&g_deg[t.w], 1);
    } else {
        for (int e = i; e < E; e++) atomicAdd(&g_deg[__ldg(tidx + e)], 1);
    }
}

// ---------------------------------------------------------------------------
// Kernel 3: exclusive scan -> g_off, g_cursor. One block, warp-shuffle scan.
// ---------------------------------------------------------------------------
__global__ void scan_kernel() {
    __shared__ int warp_tot[32];
    __shared__ int carry_sh;
    int tid  = threadIdx.x;
    int lane = tid & 31;
    int wid  = tid >> 5;
    if (tid == 0) carry_sh = 0;
    __syncthreads();

    for (int base = 0; base < VNUM; base += 1024) {
        int i = base + tid;
        int x = (i < VNUM) ? g_deg[i] : 0;

        int incl = x;
#pragma unroll
        for (int ofs = 1; ofs < 32; ofs <<= 1) {
            int v = __shfl_up_sync(0xffffffffu, incl, ofs);
            if (lane >= ofs) incl += v;
        }
        if (lane == 31) warp_tot[wid] = incl;
        __syncthreads();

        if (wid == 0) {
            int t = warp_tot[lane];
            int s = t;
#pragma unroll
            for (int ofs = 1; ofs < 32; ofs <<= 1) {
                int v = __shfl_up_sync(0xffffffffu, s, ofs);
                if (lane >= ofs) s += v;
            }
            warp_tot[lane] = s - t;
        }
        __syncthreads();

        int carry = carry_sh;
        int excl = carry + warp_tot[wid] + incl - x;
        if (i < VNUM) {
            g_off[i] = excl;
            g_cursor[i] = excl;
        }
        __syncthreads();
        if (tid == 1023) carry_sh = carry + warp_tot[31] + incl;
        __syncthreads();
    }
    if (tid == 0) g_off[VNUM] = carry_sh;
}

// ---------------------------------------------------------------------------
// Kernel 4: fill CSR slots, 4 edges per thread (vector loads, MLP=4)
// ---------------------------------------------------------------------------
__global__ void fill_kernel(const int* __restrict__ sidx,
                            const int* __restrict__ tidx,
                            const float* __restrict__ enorm,
                            const float* __restrict__ esgn,
                            int E) {
    int i = (blockIdx.x * blockDim.x + threadIdx.x) * 4;
    if (i + 3 < E) {
        int4   s = __ldg((const int4*)(sidx + i));
        int4   t = __ldg((const int4*)(tidx + i));
        float4 n = __ldg((const float4*)(enorm + i));
        float4 g = __ldg((const float4*)(esgn + i));
        int p0 = atomicAdd(&g_cursor[t.x], 1);
        int p1 = atomicAdd(&g_cursor[t.y], 1);
        int p2 = atomicAdd(&g_cursor[t.z], 1);
        int p3 = atomicAdd(&g_cursor[t.w], 1);
        g_sw[p0] = make_int2(s.x, __float_as_int(n.x * g.x));
        g_sw[p1] = make_int2(s.y, __float_as_int(n.y * g.y));
        g_sw[p2] = make_int2(s.z, __float_as_int(n.z * g.z));
        g_sw[p3] = make_int2(s.w, __float_as_int(n.w * g.w));
    } else {
        for (int e = i; e < E; e++) {
            int t = __ldg(tidx + e);
            int pos = atomicAdd(&g_cursor[t], 1);
            float w = __ldg(enorm + e) * __ldg(esgn + e);
            g_sw[pos] = make_int2(__ldg(sidx + e), __float_as_int(w));
        }
    }
}

// ---------------------------------------------------------------------------
// Kernel 5: split weights to bf16 hi/lo, row-major [256][128].
// Row n: n<128 -> loc_w row n; n>=128 -> std_w row n-128.
// ---------------------------------------------------------------------------
__global__ void wconv_kernel(const float* __restrict__ lw,
                             const float* __restrict__ sw) {
    int idx = blockIdx.x * blockDim.x + threadIdx.x;
    if (idx >= 256 * 128) return;
    int n = idx >> 7;
    int k = idx & 127;
    float w = (n < 128) ? lw[n * 128 + k] : sw[(n - 128) * 128 + k];
    __nv_bfloat16 hi = __float2bfloat16(w);
    __nv_bfloat16 lo = __float2bfloat16(w - __bfloat162float(hi));
    g_Bhi[idx] = hi;
    g_Blo[idx] = lo;
}

// ---------------------------------------------------------------------------
// Kernel 6: convert vrepr fp32 -> fp16 (halves gather traffic).
// Each thread: one float4 -> 4 halves (uint2 store).
// ---------------------------------------------------------------------------
__global__ void vconv_kernel(const float* __restrict__ vrepr) {
    int i = blockIdx.x * blockDim.x + threadIdx.x;
    const int n4 = VNUM * OUTD / 4;
    if (i >= n4) return;
    float4 v = __ldg((const float4*)vrepr + i);
    __half2 h01 = __floats2half2_rn(v.x, v.y);
    __half2 h23 = __floats2half2_rn(v.z, v.w);
    uint2 p;
    p.x = *(uint32_t*)&h01;
    p.y = *(uint32_t*)&h23;
    *((uint2*)g_vrh + i) = p;
}

// ---------------------------------------------------------------------------
// Kernel 7: gather-aggregate. One warp per target row, batched coalesced edge
// loads + shfl broadcast, 4-deep gather MLP. fp16 source rows (256 B/edge),
// fp32 accumulation, one STG.128 per lane. No float atomics.
// ---------------------------------------------------------------------------
__global__ void gather_kernel() {
    int v = (blockIdx.x * blockDim.x + threadIdx.x) >> 5;
    int lane = threadIdx.x & 31;
    if (v >= VNUM) return;

    int beg = __ldg(&g_off[v]);
    int end = __ldg(&g_off[v + 1]);

    float4 acc = make_float4(0.f, 0.f, 0.f, 0.f);
    const uint2* vrh = (const uint2*)g_vrh;    // 32 uint2 per row (4 halves each)
    const unsigned FULL = 0xffffffffu;

    for (int base = beg; base < end; base += 32) {
        int rem = end - base;
        int n = rem < 32 ? rem : 32;
        int2 rec = make_int2(0, 0);
        if (lane < n) rec = __ldg(&g_sw[base + lane]);

        if (n == 32) {
#pragma unroll
            for (int j = 0; j < 32; j += 4) {
                int s0 = __shfl_sync(FULL, rec.x, j);
                int s1 = __shfl_sync(FULL, rec.x, j + 1);
                int s2 = __shfl_sync(FULL, rec.x, j + 2);
                int s3 = __shfl_sync(FULL, rec.x, j + 3);
                float w0 = __int_as_float(__shfl_sync(FULL, rec.y, j));
                float w1 = __int_as_float(__shfl_sync(FULL, rec.y, j + 1));
                float w2 = __int_as_float(__shfl_sync(FULL, rec.y, j + 2));
                float w3 = __int_as_float(__shfl_sync(FULL, rec.y, j + 3));
                uint2 p0 = __ldg(vrh + (size_t)s0 * 32 + lane);
                uint2 p1 = __ldg(vrh + (size_t)s1 * 32 + lane);
                uint2 p2 = __ldg(vrh + (size_t)s2 * 32 + lane);
                uint2 p3 = __ldg(vrh + (size_t)s3 * 32 + lane);
                float2 a01, a23;
                a01 = __half22float2(*(__half2*)&p0.x); a23 = __half22float2(*(__half2*)&p0.y);
                acc.x += w0 * a01.x; acc.y += w0 * a01.y; acc.z += w0 * a23.x; acc.w += w0 * a23.y;
                a01 = __half22float2(*(__half2*)&p1.x); a23 = __half22float2(*(__half2*)&p1.y);
                acc.x += w1 * a01.x; acc.y += w1 * a01.y; acc.z += w1 * a23.x; acc.w += w1 * a23.y;
                a01 = __half22float2(*(__half2*)&p2.x); a23 = __half22float2(*(__half2*)&p2.y);
                acc.x += w2 * a01.x; acc.y += w2 * a01.y; acc.z += w2 * a23.x; acc.w += w2 * a23.y;
                a01 = __half22float2(*(__half2*)&p3.x); a23 = __half22float2(*(__half2*)&p3.y);
                acc.x += w3 * a01.x; acc.y += w3 * a01.y; acc.z += w3 * a23.x; acc.w += w3 * a23.y;
            }
        } else {
            for (int j = 0; j < n; j++) {
                int s = __shfl_sync(FULL, rec.x, j);
                float w = __int_as_float(__shfl_sync(FULL, rec.y, j));
                uint2 p = __ldg(vrh + (size_t)s * 32 + lane);
                float2 a01 = __half22float2(*(__half2*)&p.x);
                float2 a23 = __half22float2(*(__half2*)&p.y);
                acc.x += w * a01.x; acc.y += w * a01.y;
                acc.z += w * a23.x; acc.w += w * a23.y;
            }
        }
    }
    ((float4*)g_ptr)[(size_t)v * 32 + lane] = acc;
}

// ---------------------------------------------------------------------------
// Kernel 8: dual GEMM + bias + softplus via mma.sync bf16 3-split.
//   D = Ahi*Bhi + Alo*Bhi + Ahi*Blo   (error ~2^-16)
// Block: 256 threads / 8 warps, 64 rows x 256 cols (N=256 = loc|std).
// ---------------------------------------------------------------------------
#define SM_AHI 0
#define SM_ALO (64 * PADK * 2)                     // 17408
#define SM_BHI (2 * 64 * PADK * 2)                 // 34816
#define SM_BLO (2 * 64 * PADK * 2 + 256 * PADK * 2)// 104448
#define GEMM_SMEM (2 * 64 * PADK * 2 + 2 * 256 * PADK * 2)  // 174080

__global__ void __launch_bounds__(256, 1)
gemm_kernel(const float* __restrict__ lb,
            const float* __restrict__ sb,
            float* __restrict__ out) {
    extern __shared__ __align__(16) uint8_t smem[];
    __nv_bfloat16* shAhi = (__nv_bfloat16*)(smem + SM_AHI);
    __nv_bfloat16* shAlo = (__nv_bfloat16*)(smem + SM_ALO);
    __nv_bfloat16* shBhi = (__nv_bfloat16*)(smem + SM_BHI);
    __nv_bfloat16* shBlo = (__nv_bfloat16*)(smem + SM_BLO);

    int tid = threadIdx.x;
    int row0 = blockIdx.x * 64;

    // Stage A: read fp32 g_ptr, split into bf16 hi/lo. 2048 float4 / 256 thr.
    for (int i = tid; i < 2048; i += 256) {
        int r = i >> 5;
        int c4 = i & 31;
        int row = row0 + r;
        float4 v = (row < VNUM) ? __ldg((const float4*)g_ptr + (size_t)row * 32 + c4)
                                : make_float4(0.f, 0.f, 0.f, 0.f);
        __nv_bfloat16 h0 = __float2bfloat16(v.x), h1 = __float2bfloat16(v.y);
        __nv_bfloat16 h2 = __float2bfloat16(v.z), h3 = __float2bfloat16(v.w);
        __nv_bfloat16 l0 = __float2bfloat16(v.x - __bfloat162float(h0));
        __nv_bfloat16 l1 = __float2bfloat16(v.y - __bfloat162float(h1));
        __nv_bfloat16 l2 = __float2bfloat16(v.z - __bfloat162float(h2));
        __nv_bfloat16 l3 = __float2bfloat16(v.w - __bfloat162float(h3));
        uint2 hp, lp;
        hp.x = (uint32_t)__bfloat16_as_ushort(h0) | ((uint32_t)__bfloat16_as_ushort(h1) << 16);
        hp.y = (uint32_t)__bfloat16_as_ushort(h2) | ((uint32_t)__bfloat16_as_ushort(h3) << 16);
        lp.x = (uint32_t)__bfloat16_as_ushort(l0) | ((uint32_t)__bfloat16_as_ushort(l1) << 16);
        lp.y = (uint32_t)__bfloat16_as_ushort(l2) | ((uint32_t)__bfloat16_as_ushort(l3) << 16);
        *(uint2*)(shAhi + r * PADK + c4 * 4) = hp;
        *(uint2*)(shAlo + r * PADK + c4 * 4) = lp;
    }
    // Stage B: 256 rows x 16 uint4 (8 bf16 each) per matrix.
    for (int i = tid; i < 4096; i += 256) {
        int n = i >> 4;
        int c8 = i & 15;
        *(uint4*)(shBhi + n * PADK + c8 * 8) = *((const uint4*)g_Bhi + (size_t)n * 16 + c8);
        *(uint4*)(shBlo + n * PADK + c8 * 8) = *((const uint4*)g_Blo + (size_t)n * 16 + c8);
    }
    __syncthreads();

    int warp = tid >> 5;
    int lane = tid & 31;
    int warp_m = warp & 3;
    int col_half = warp >> 2;
    int g = lane >> 2;
    int tg = lane & 3;

    const __nv_bfloat16* Ah = shAhi + (warp_m * 16 + g) * PADK;
    const __nv_bfloat16* Al = shAlo + (warp_m * 16 + g) * PADK;

    float acc[16][4];
#pragma unroll
    for (int t = 0; t < 16; t++)
        acc[t][0] = acc[t][1] = acc[t][2] = acc[t][3] = 0.f;

#pragma unroll
    for (int ks = 0; ks < 8; ks++) {
        int k0 = ks * 16 + tg * 2;
        uint32_t ah[4], al[4];
        ah[0] = *(const uint32_t*)(Ah + k0);
        ah[1] = *(const uint32_t*)(Ah + 8 * PADK + k0);
        ah[2] = *(const uint32_t*)(Ah + k0 + 8);
        ah[3] = *(const uint32_t*)(Ah + 8 * PADK + k0 + 8);
        al[0] = *(const uint32_t*)(Al + k0);
        al[1] = *(const uint32_t*)(Al + 8 * PADK + k0);
        al[2] = *(const uint32_t*)(Al + k0 + 8);
        al[3] = *(const uint32_t*)(Al + 8 * PADK + k0 + 8);

#pragma unroll
        for (int nt = 0; nt < 16; nt++) {
            int n = col_half * 128 + nt * 8 + g;
            const __nv_bfloat16* Bh = shBhi + n * PADK;
            const __nv_bfloat16* Bl = shBlo + n * PADK;
            uint32_t bh[2], bl[2];
            bh[0] = *(const uint32_t*)(Bh + k0);
            bh[1] = *(const uint32_t*)(Bh + k0 + 8);
            bl[0] = *(const uint32_t*)(Bl + k0);
            bl[1] = *(const uint32_t*)(Bl + k0 + 8);
            mma16816(acc[nt], ah, bh);
            mma16816(acc[nt], al, bh);
            mma16816(acc[nt], ah, bl);
        }
    }

    int row_a = row0 + warp_m * 16 + g;
    int row_b = row_a + 8;
    float* out_loc = out;
    float* out_std = out + (size_t)VNUM * OUTD;

#pragma unroll
    for (int nt = 0; nt < 16; nt++) {
        int ncol = col_half * 128 + nt * 8 + tg * 2;
        if (ncol < 128) {
            float b0 = __ldg(lb + ncol), b1 = __ldg(lb + ncol + 1);
            if (row_a < VNUM) {
                float2 o = make_float2(acc[nt][0] + b0, acc[nt][1] + b1);
                *(float2*)(out_loc + (size_t)row_a * OUTD + ncol) = o;
            }
            if (row_b < VNUM) {
                float2 o = make_float2(acc[nt][2] + b0, acc[nt][3] + b1);
                *(float2*)(out_loc + (size_t)row_b * OUTD + ncol) = o;
            }
        } else {
            int sc = ncol - 128;
            float b0 = __ldg(sb + sc), b1 = __ldg(sb + sc + 1);
            if (row_a < VNUM) {
                float x0 = acc[nt][0] + b0, x1 = acc[nt][1] + b1;
                float2 o;
                o.x = fmaxf(x0, 0.f) + log1pf(expf(-fabsf(x0))) + EPS_F;
                o.y = fmaxf(x1, 0.f) + log1pf(expf(-fabsf(x1))) + EPS_F;
                *(float2*)(out_std + (size_t)row_a * OUTD + sc) = o;
            }
            if (row_b < VNUM) {
                float x0 = acc[nt][2] + b0, x1 = acc[nt][3] + b1;
                float2 o;
                o.x = fmaxf(x0, 0.f) + log1pf(expf(-fabsf(x0))) + EPS_F;
                o.y = fmaxf(x1, 0.f) + log1pf(expf(-fabsf(x1))) + EPS_F;
                *(float2*)(out_std + (size_t)row_b * OUTD + sc) = o;
            }
        }
    }
}

// ---------------------------------------------------------------------------
// Launch. Inputs: sidx, tidx, enorm, esgn, vrepr, loc_w, loc_b, std_w, std_b
// Output: [loc (VNUM*128), std (VNUM*128)] fp32
// ---------------------------------------------------------------------------
extern "C" void kernel_launch(void* const* d_in, const int* in_sizes, int n_in,
                              void* d_out, int out_size) {
    const int*   sidx  = (const int*)d_in[0];
    const int*   tidx  = (const int*)d_in[1];
    const float* enorm = (const float*)d_in[2];
    const float* esgn  = (const float*)d_in[3];
    const float* vrepr = (const float*)d_in[4];
    const float* lw    = (const float*)d_in[5];
    const float* lb    = (const float*)d_in[6];
    const float* sw    = (const float*)d_in[7];
    const float* sb    = (const float*)d_in[8];
    float* out = (float*)d_out;
    int E = in_sizes[0];
    if (E > EMAX) E = EMAX;

    (void)cudaFuncSetAttribute(gemm_kernel,
                               cudaFuncAttributeMaxDynamicSharedMemorySize, GEMM_SMEM);

    // 1) zero degree counters
    zero_deg_kernel<<<(VNUM + 255) / 256, 256>>>();
    // 2) count edges per target (4/thread)
    count_kernel<<<((E + 3) / 4 + 255) / 256, 256>>>(tidx, E);
    // 3) exclusive scan -> CSR offsets + cursors
    scan_kernel<<<1, 1024>>>();
    // 4) fill CSR (4/thread)
    fill_kernel<<<((E + 3) / 4 + 255) / 256, 256>>>(sidx, tidx, enorm, esgn, E);
    // 5) weights -> bf16 hi/lo
    wconv_kernel<<<(256 * 128 + 255) / 256, 256>>>(lw, sw);
    // 6) vrepr -> fp16
    vconv_kernel<<<(VNUM * OUTD / 4 + 255) / 256, 256>>>(vrepr);
    // 7) gather-aggregate (fp16 rows) -> fp32 ptr
    gather_kernel<<<(VNUM * 32 + 255) / 256, 256>>>();
    // 8) dual GEMM + bias + softplus (mma.sync bf16 3-split)
    gemm_kernel<<<(VNUM + 63) / 64, 256, GEMM_SMEM>>>(lb, sb, out);
}